// round 14
// baseline (speedup 1.0000x reference)
#include <cuda_runtime.h>
#include <cuda_fp16.h>
#include <cstdint>
#include <cstddef>

#define NU 100000
#define NI 200000
#define BB 3
#define EE 1000000
#define DD 64

// Scratch (device globals: allocation-free per harness rules)
__device__ float    g_uscr[(size_t)BB * NU * DD];   // 76.8 MB  pre-activations
__device__ float    g_iscr[(size_t)BB * NI * DD];   // 153.6 MB pre-activations
__device__ __half   g_z16_u[(size_t)NU * DD];       // 12.8 MB  f16(user_emb @ i_w)
__device__ __half   g_z16_i[(size_t)NI * DD];       // 25.6 MB  f16(item_emb @ u_w)
__device__ uint32_t g_w32_iw[DD * DD];              // tf32 i_w (for Z_u)
__device__ uint32_t g_w32_uw[DD * DD];              // tf32 u_w (for Z_i)

// ---------------------------------------------------------------------------
// W -> tf32
// ---------------------------------------------------------------------------
__device__ __forceinline__ uint32_t to_tf32(float x) {
    uint32_t v;
    asm("cvt.rna.tf32.f32 %0, %1;" : "=r"(v) : "f"(x));
    return v;
}
__global__ void __launch_bounds__(256) w_to_tf32(
    const float* __restrict__ w, uint32_t* __restrict__ out)
{
    int i = blockIdx.x * blockDim.x + threadIdx.x;
    if (i < DD * DD) out[i] = to_tf32(w[i]);
}

// ---------------------------------------------------------------------------
// Z-GEMM: Z16 = f16(X @ W)   (tf32 mma, 32-row tiles, RNA staging)
// ---------------------------------------------------------------------------
#define MMA_TF32(c0,c1,c2,c3, a0,a1,a2,a3, b0,b1)                            \
    asm volatile("mma.sync.aligned.m16n8k8.row.col.f32.tf32.tf32.f32 "       \
        "{%0,%1,%2,%3}, {%4,%5,%6,%7}, {%8,%9}, {%0,%1,%2,%3};"              \
        : "+f"(c0), "+f"(c1), "+f"(c2), "+f"(c3)                             \
        : "r"(a0), "r"(a1), "r"(a2), "r"(a3), "r"(b0), "r"(b1))

#define XSTRIDE 68

__global__ void __launch_bounds__(256, 4) z_gemm(
    const float*    __restrict__ X,     // [N, 64] fp32
    const uint32_t* __restrict__ W32,   // [64, 64] tf32 (k, n)
    __half*         __restrict__ Z,     // [N, 64] fp16
    int N)
{
    __shared__ uint32_t sX[32 * XSTRIDE];   // 8.5 KB

    int t  = threadIdx.x;
    int n0 = blockIdx.x * 32;

    // Stage X tile with RNA conversion (accuracy): 512 uint4, 2 per thread
    const float4* X4 = reinterpret_cast<const float4*>(X);
    #pragma unroll
    for (int i = 0; i < 2; i++) {
        int u  = t + i * 256;             // 0..511
        int r  = u >> 4;
        int kq = u & 15;
        float4 x = X4[((size_t)n0 + r) * 16 + kq];
        uint4 xt;
        xt.x = to_tf32(x.x); xt.y = to_tf32(x.y);
        xt.z = to_tf32(x.z); xt.w = to_tf32(x.w);
        *reinterpret_cast<uint4*>(&sX[r * XSTRIDE + kq * 4]) = xt;
    }
    __syncthreads();

    int warp = t >> 5, lane = t & 31;
    int gid = lane >> 2, tig = lane & 3;
    int mt = warp & 1;
    int nq = warp >> 1;

    int r0l = mt * 16 + gid;
    int r1l = r0l + 8;

    float acc[2][4];
    #pragma unroll
    for (int nt = 0; nt < 2; nt++)
        #pragma unroll
        for (int q = 0; q < 4; q++) acc[nt][q] = 0.0f;

    #pragma unroll
    for (int ks = 0; ks < 8; ks++) {
        int k0 = ks * 8;
        uint32_t bf[2][2];
        #pragma unroll
        for (int nt = 0; nt < 2; nt++) {
            int col = nq * 16 + nt * 8 + gid;
            bf[nt][0] = __ldg(&W32[(k0 + tig) * 64 + col]);
            bf[nt][1] = __ldg(&W32[(k0 + tig + 4) * 64 + col]);
        }
        uint32_t a0 = sX[r0l * XSTRIDE + k0 + tig];
        uint32_t a1 = sX[r1l * XSTRIDE + k0 + tig];
        uint32_t a2 = sX[r0l * XSTRIDE + k0 + tig + 4];
        uint32_t a3 = sX[r1l * XSTRIDE + k0 + tig + 4];
        #pragma unroll
        for (int nt = 0; nt < 2; nt++)
            MMA_TF32(acc[nt][0], acc[nt][1], acc[nt][2], acc[nt][3],
                     a0, a1, a2, a3, bf[nt][0], bf[nt][1]);
    }

    int r0 = n0 + r0l, r1 = n0 + r1l;
    #pragma unroll
    for (int nt = 0; nt < 2; nt++) {
        int c0 = nq * 16 + nt * 8 + 2 * tig;
        *reinterpret_cast<__half2*>(Z + (size_t)r0 * 64 + c0)
            = __floats2half2_rn(acc[nt][0], acc[nt][1]);
        *reinterpret_cast<__half2*>(Z + (size_t)r1 * 64 + c0)
            = __floats2half2_rn(acc[nt][2], acc[nt][3]);
    }
}

// ---------------------------------------------------------------------------
// Scatter: COO spmm  out[row] += val * Z16[col]  (red.global.add.v4.f32)
// ---------------------------------------------------------------------------
__global__ void __launch_bounds__(256) scatter_kernel(
    const float*  __restrict__ vals,
    const int*    __restrict__ rows,
    const int*    __restrict__ cols,
    const __half* __restrict__ dense,   // [n_cols, 64] fp16
    float*        __restrict__ out,     // [N, 64] fp32
    int nE)
{
    int lane   = threadIdx.x & 31;
    int warpId = (blockIdx.x * blockDim.x + threadIdx.x) >> 5;
    int nWarps = (gridDim.x * blockDim.x) >> 5;
    int half_  = lane >> 4;
    int l4     = lane & 15;

    for (int base = warpId * 32; base < nE; base += nWarps * 32) {
        int e = base + lane;
        float v = 0.0f; int r = 0, c = 0;
        if (e < nE) { v = vals[e]; r = rows[e]; c = cols[e]; }

        #pragma unroll
        for (int i = 0; i < 16; i++) {
            int src = 2 * i + half_;
            float vv = __shfl_sync(0xffffffffu, v, src);
            int   rr = __shfl_sync(0xffffffffu, r, src);
            int   cc = __shfl_sync(0xffffffffu, c, src);

            const uint2* dp = reinterpret_cast<const uint2*>(dense + (size_t)cc * DD) + l4;
            uint2 raw = __ldg(dp);
            __half2 h0 = *reinterpret_cast<__half2*>(&raw.x);
            __half2 h1 = *reinterpret_cast<__half2*>(&raw.y);
            float2 f0 = __half22float2(h0);
            float2 f1 = __half22float2(h1);

            float4 p;
            p.x = vv * f0.x; p.y = vv * f0.y; p.z = vv * f1.x; p.w = vv * f1.y;

            float* op = out + (size_t)rr * DD + (size_t)l4 * 4;
            asm volatile("red.global.add.v4.f32 [%0], {%1,%2,%3,%4};"
                         :: "l"(op), "f"(p.x), "f"(p.y), "f"(p.z), "f"(p.w)
                         : "memory");
        }
    }
}

// ---------------------------------------------------------------------------
// Fused elementwise epilogue (both sides in one grid):
// per-behavior sigmoid + sigmoid(mean of pre-activations). Pure streaming.
// ---------------------------------------------------------------------------
__device__ __forceinline__ float sigmoidf_(float x) {
    return 1.0f / (1.0f + __expf(-x));
}

__global__ void __launch_bounds__(256) epilogue_dual(
    const float* __restrict__ scr_u, float* __restrict__ per_u, float* __restrict__ mean_u,
    const float* __restrict__ scr_i, float* __restrict__ per_i, float* __restrict__ mean_i,
    int nblk_u)
{
    const float* scr; float* per; float* mean; int N; int blk;
    if ((int)blockIdx.x < nblk_u) {
        blk = blockIdx.x;          scr = scr_u; per = per_u; mean = mean_u; N = NU;
    } else {
        blk = blockIdx.x - nblk_u; scr = scr_i; per = per_i; mean = mean_i; N = NI;
    }

    size_t idx    = (size_t)blk * 256 + threadIdx.x;   // float4 index in slice
    size_t stride = (size_t)N * 16;

    const float4* s4 = reinterpret_cast<const float4*>(scr);
    float4* p4 = reinterpret_cast<float4*>(per);
    float4* m4 = reinterpret_cast<float4*>(mean);

    float4 s0 = s4[idx];
    float4 s1 = s4[idx + stride];
    float4 s2 = s4[idx + 2 * stride];

    float4 o;
    o.x = sigmoidf_(s0.x); o.y = sigmoidf_(s0.y); o.z = sigmoidf_(s0.z); o.w = sigmoidf_(s0.w);
    p4[idx] = o;
    o.x = sigmoidf_(s1.x); o.y = sigmoidf_(s1.y); o.z = sigmoidf_(s1.z); o.w = sigmoidf_(s1.w);
    p4[idx + stride] = o;
    o.x = sigmoidf_(s2.x); o.y = sigmoidf_(s2.y); o.z = sigmoidf_(s2.z); o.w = sigmoidf_(s2.w);
    p4[idx + 2 * stride] = o;

    const float third = 1.0f / 3.0f;
    float4 m;
    m.x = sigmoidf_((s0.x + s1.x + s2.x) * third);
    m.y = sigmoidf_((s0.y + s1.y + s2.y) * third);
    m.z = sigmoidf_((s0.z + s1.z + s2.z) * third);
    m.w = sigmoidf_((s0.w + s1.w + s2.w) * third);
    m4[idx] = m;
}

// ---------------------------------------------------------------------------
// Lazy stream/event creation (first call = correctness run, outside capture).
// ---------------------------------------------------------------------------
static cudaStream_t side_stream() {
    static cudaStream_t s = nullptr;
    if (!s) cudaStreamCreateWithFlags(&s, cudaStreamNonBlocking);
    return s;
}
static cudaEvent_t ev(int i) {
    static cudaEvent_t e[8] = {};
    if (!e[i]) cudaEventCreateWithFlags(&e[i], cudaEventDisableTiming);
    return e[i];
}

// ---------------------------------------------------------------------------
// Launch DAG:
//   stream0: memset iscr[0] ─(wait zu)─ i2u[0] ─(wait s1)─ i2u[1] ─(wait s2)─
//            i2u[2] ─(wait mu,zi)─ u2i x3 ─ epilogue_dual
//   s1:      w32(i_w) ─ z_gemm_u (e_zu) ─ memset iscr[1] (e_s1) ─
//            memset iscr[2] (e_s2) ─ memset uscr (e_mu) ─ w32(u_w) ─
//            z_gemm_i (e_zi)
// ---------------------------------------------------------------------------
extern "C" void kernel_launch(void* const* d_in, const int* in_sizes, int n_in,
                              void* d_out, int out_size)
{
    const float* user_emb = (const float*)d_in[0];
    const float* item_emb = (const float*)d_in[1];
    const float* u2i_vals = (const float*)d_in[2];
    const int*   u2i_rows = (const int*)  d_in[3];
    const int*   u2i_cols = (const int*)  d_in[4];
    const float* i2u_vals = (const float*)d_in[5];
    const int*   i2u_rows = (const int*)  d_in[6];
    const int*   i2u_cols = (const int*)  d_in[7];
    const float* u_w      = (const float*)d_in[8];
    const float* i_w      = (const float*)d_in[9];

    float* out     = (float*)d_out;
    float* out_ue  = out;                                                 // [NU,64]
    float* out_ie  = out + (size_t)NU * DD;                               // [NI,64]
    float* out_ues = out + (size_t)(NU + NI) * DD;                        // [3,NU,64]
    float* out_ies = out + (size_t)(NU + NI) * DD + (size_t)BB * NU * DD; // [3,NI,64]

    void* p;
    cudaGetSymbolAddress(&p, g_uscr);    float*    uscr  = (float*)p;
    cudaGetSymbolAddress(&p, g_iscr);    float*    iscr  = (float*)p;
    cudaGetSymbolAddress(&p, g_z16_u);   __half*   z16u  = (__half*)p;
    cudaGetSymbolAddress(&p, g_z16_i);   __half*   z16i  = (__half*)p;
    cudaGetSymbolAddress(&p, g_w32_iw);  uint32_t* w32iw = (uint32_t*)p;
    cudaGetSymbolAddress(&p, g_w32_uw);  uint32_t* w32uw = (uint32_t*)p;

    cudaStream_t s1 = side_stream();
    cudaEvent_t e_fork = ev(0), e_zu = ev(1), e_s1 = ev(2), e_s2 = ev(3),
                e_mu = ev(4), e_zi = ev(5);

    const size_t ISLICE = (size_t)NI * DD * sizeof(float);

    cudaEventRecord(e_fork, 0);
    cudaStreamWaitEvent(s1, e_fork, 0);

    // s1: Z_u first (unblocks i2u), then memsets, then Z_i (unblocks u2i)
    w_to_tf32<<<16, 256, 0, s1>>>(i_w, w32iw);
    z_gemm<<<NU / 32, 256, 0, s1>>>(user_emb, w32iw, z16u, NU);
    cudaEventRecord(e_zu, s1);
    cudaMemsetAsync((char*)iscr + ISLICE, 0, ISLICE, s1);
    cudaEventRecord(e_s1, s1);
    cudaMemsetAsync((char*)iscr + 2 * ISLICE, 0, ISLICE, s1);
    cudaEventRecord(e_s2, s1);
    cudaMemsetAsync(uscr, 0, sizeof(g_uscr), s1);
    cudaEventRecord(e_mu, s1);
    w_to_tf32<<<16, 256, 0, s1>>>(u_w, w32uw);
    z_gemm<<<NI / 32, 256, 0, s1>>>(item_emb, w32uw, z16i, NI);
    cudaEventRecord(e_zi, s1);

    // stream0: memset iscr slice 0 only
    cudaMemsetAsync(iscr, 0, ISLICE, 0);

    const int FULL_GRID = (EE + 255) / 256;

    cudaStreamWaitEvent(0, e_zu, 0);
    scatter_kernel<<<FULL_GRID, 256>>>(
        i2u_vals, i2u_rows, i2u_cols, z16u, iscr, EE);
    cudaStreamWaitEvent(0, e_s1, 0);
    scatter_kernel<<<FULL_GRID, 256>>>(
        i2u_vals + (size_t)EE, i2u_rows + (size_t)EE, i2u_cols + (size_t)EE,
        z16u, iscr + (size_t)NI * DD, EE);
    cudaStreamWaitEvent(0, e_s2, 0);
    scatter_kernel<<<FULL_GRID, 256>>>(
        i2u_vals + 2 * (size_t)EE, i2u_rows + 2 * (size_t)EE, i2u_cols + 2 * (size_t)EE,
        z16u, iscr + 2 * (size_t)NI * DD, EE);

    cudaStreamWaitEvent(0, e_mu, 0);
    cudaStreamWaitEvent(0, e_zi, 0);
    for (int b = 0; b < BB; b++) {
        scatter_kernel<<<FULL_GRID, 256>>>(
            u2i_vals + (size_t)b * EE, u2i_rows + (size_t)b * EE,
            u2i_cols + (size_t)b * EE, z16i,
            uscr + (size_t)b * NU * DD, EE);
    }

    // fused elementwise epilogue (both sides, one grid)
    const int NBLK_U = NU * 16 / 256;   // 6250
    const int NBLK_I = NI * 16 / 256;   // 12500
    epilogue_dual<<<NBLK_U + NBLK_I, 256>>>(
        uscr, out_ues, out_ue,
        iscr, out_ies, out_ie,
        NBLK_U);
}